// round 16
// baseline (speedup 1.0000x reference)
#include <cuda_runtime.h>
#include <cuda_fp16.h>
#include <math_constants.h>
#include <cstdint>

// ---------------------------------------------------------------------------
// SelfAttention via split-fp16 mma.sync GEMMs (fp32-accurate; plain sm_103).
// a = a_hi + a_lo (fp16 each); GEMMs use 3 products (Ah@Bh + Ah@Bl + Al@Bh);
// PV uses 2 (Pl dropped); V projection uses 2 (x_lo dropped).
// Round 13: CTA tile 128x128 with NSTAGE=3 (64KB/stage x3 = 192KB smem):
// loads issue BEFORE compute each iter (no WAR on the compute buffer) and
// only ONE __syncthreads per iteration — removes the NSTAGE=2 serial load
// phase that capped tensor pipe at 66%.
// ---------------------------------------------------------------------------

#define SN 4096
#define SD 1024
#define BM 128
#define BN 128
#define BKE 64                    // K elems (fp16) per stage = 128 bytes/row
#define NSTAGE 3
#define NTHR 512
#define TILEB 16384               // 128 rows x 128 bytes
#define STAGEB (4 * TILEB)        // Ah, Al, Bh, Bl = 65536
#define SMEMB (NSTAGE * STAGEB)   // 196608 bytes

// ------------------------- scratch ----------------------------------------
static __device__ float   g_S[(size_t)SN * SN];
static __device__ float   g_O2[(size_t)SN * SD];
static __device__ __half  g_xh[SN * SD],  g_xl[SN * SD];
static __device__ __half  g_Wth[3][SD * SD], g_Wtl[3][SD * SD];
static __device__ __half  g_Qh[SN * SD],  g_Ql[SN * SD];
static __device__ __half  g_Kh[SN * SD],  g_Kl[SN * SD];
static __device__ __half  g_Vth[(size_t)SD * SN], g_Vtl[(size_t)SD * SN];
static __device__ __half  g_Ph[(size_t)SN * SN];

// ------------------------- PTX helpers ------------------------------------
__device__ __forceinline__ uint32_t smem_u32(const void* p) {
    uint32_t a;
    asm("{ .reg .u64 t; cvta.to.shared.u64 t, %1; cvt.u32.u64 %0, t; }"
        : "=r"(a) : "l"(p));
    return a;
}
__device__ __forceinline__ uint32_t swz(uint32_t o) { return o ^ ((o >> 3) & 0x70); }

__device__ __forceinline__ void cp16(uint32_t dst, const void* src) {
    asm volatile("cp.async.cg.shared.global [%0], [%1], 16;\n" :: "r"(dst), "l"(src));
}
#define CP_COMMIT() asm volatile("cp.async.commit_group;\n" ::: "memory")
#define CP_WAIT1()  asm volatile("cp.async.wait_group 1;\n" ::: "memory")

__device__ __forceinline__ void ldm_x4(uint32_t* r, uint32_t addr) {
    asm volatile("ldmatrix.sync.aligned.m8n8.x4.shared.b16 {%0,%1,%2,%3}, [%4];"
        : "=r"(r[0]), "=r"(r[1]), "=r"(r[2]), "=r"(r[3]) : "r"(addr));
}
__device__ __forceinline__ void mma16816(float* c, const uint32_t* a, const uint32_t* b) {
    asm volatile("mma.sync.aligned.m16n8k16.row.col.f32.f16.f16.f32 "
        "{%0,%1,%2,%3}, {%4,%5,%6,%7}, {%8,%9}, {%0,%1,%2,%3};"
        : "+f"(c[0]), "+f"(c[1]), "+f"(c[2]), "+f"(c[3])
        : "r"(a[0]), "r"(a[1]), "r"(a[2]), "r"(a[3]), "r"(b[0]), "r"(b[1]));
}

__device__ __forceinline__ void split_store2(__half* Hh, __half* Hl, size_t o,
                                             float v0, float v1) {
    const __half h0 = __float2half(v0), h1 = __float2half(v1);
    const __half l0 = __float2half(v0 - __half2float(h0));
    const __half l1 = __float2half(v1 - __half2float(h1));
    *reinterpret_cast<__half2*>(Hh + o) = __halves2half2(h0, h1);
    *reinterpret_cast<__half2*>(Hl + o) = __halves2half2(l0, l1);
}

// ------------------------- GEMM kernel -------------------------------------
// 512 threads, 16 warps: warp grid 4(m) x 4(n), warp tile 32x32, acc 32 regs.
// MODE 0: plain. MODE 1: scores (skip tiles fully above diag when masked).
// MODE 2: PV (K truncated at diagonal; per-row balanced 2-way split-K over bz,
//         heavy row-blocks first; bz=1 -> CfAlt).
// EPI 2: fp32 store alpha*C. EPI 3: fused QKV dispatch (bx>>3 selects weight;
//        w<2 -> row-major split store (Q/K), w==2 -> transposed split (V^T),
//        V CTAs drop the x_lo product at runtime).
// NPROD: 3 = full split, 2 = skip A_lo (loads and MMAs).
template <int MODE, int EPI, int NPROD>
__global__ void __launch_bounds__(NTHR, 1)
mm_kernel(const __half* __restrict__ Ah, const __half* __restrict__ Al, int lda,
          const __half* __restrict__ Bh, const __half* __restrict__ Bl, int ldb,
          int Kdim, float alpha,
          float* __restrict__ Cf, float* __restrict__ CfAlt,
          __half* __restrict__ Qh, __half* __restrict__ Ql,
          __half* __restrict__ Kh, __half* __restrict__ Kl,
          __half* __restrict__ Vth, __half* __restrict__ Vtl,
          int ldc, const int* __restrict__ maskedp)
{
    const int bx = blockIdx.x, bz = blockIdx.z;
    // MODE 2: reverse row order so the longest-K CTAs start in wave 1.
    const int by = (MODE == 2) ? (gridDim.y - 1 - blockIdx.y) : blockIdx.y;
    const int msk = *maskedp;
    if (MODE == 1 && msk && bx > by) return;

    int kStart = 0, kEnd = Kdim;
    if (MODE == 2) {
        const int kFull = msk ? (by + 1) * BM : Kdim;
        const int h = ((kFull >> 1) + 127) & ~127;       // balanced, 128-aligned
        if (bz == 0) { kStart = 0; kEnd = h; }
        else         { kStart = h; kEnd = kFull; }
        if (kStart >= kEnd) return;                      // by=0, z=1
    }
    const int nIter = (kEnd - kStart) / BKE;    // >= 2 always

    // effective B pointer / column base (EPI3 packs 3 weights along bx)
    const __half* BhE = Bh;
    const __half* BlE = Bl;
    int bCol0 = bx * BN;
    int wsel = 0;
    if (EPI == 3) {
        wsel = bx >> 3;
        BhE = Bh + (size_t)wsel * SD * SD;
        BlE = Bl + (size_t)wsel * SD * SD;
        bCol0 = (bx & 7) * BN;
    }
    // V projection: drop x_lo product (uniform per-CTA branch)
    const bool useLo = (NPROD == 3) && !(EPI == 3 && wsel == 2);

    extern __shared__ char smem[];
    const uint32_t sbase = smem_u32(smem);
    const int tid  = threadIdx.x;
    const int wid  = tid >> 5;
    const int lane = tid & 31;
    const int warp_m = wid & 3;                 // 4 x 32 rows
    const int warp_n = wid >> 2;                // 4 x 32 cols

    float acc[2][4][4];
#pragma unroll
    for (int mi = 0; mi < 2; mi++)
#pragma unroll
        for (int ni = 0; ni < 4; ni++)
#pragma unroll
            for (int r = 0; r < 4; r++) acc[mi][ni][r] = 0.0f;

    const int aRow0 = by * BM;

    auto load_stage = [&](int s) {
        const uint32_t st = sbase + (uint32_t)(s % NSTAGE) * STAGEB;
        const int kk = kStart + s * BKE;
#pragma unroll
        for (int j = 0; j < 2; j++) {           // A: 128 rows (hi, +lo if useLo)
            const int idx = tid + j * NTHR;     // 0..1023
            const int r = idx >> 3;
            const int c = idx & 7;
            const uint32_t sw = swz((uint32_t)(r * 128 + c * 16));
            const size_t ka = (size_t)(aRow0 + r) * lda + kk + c * 8;
            cp16(st + sw, Ah + ka);
            if (NPROD == 3) { if (useLo) cp16(st + TILEB + sw, Al + ka); }
        }
#pragma unroll
        for (int j = 0; j < 2; j++) {           // B: 128 rows hi+lo
            const int idx = tid + j * NTHR;
            const int r = idx >> 3;
            const int c = idx & 7;
            const uint32_t sw = swz((uint32_t)(r * 128 + c * 16));
            const size_t kb = (size_t)(bCol0 + r) * ldb + kk + c * 8;
            cp16(st + 2 * TILEB + sw, BhE + kb);
            cp16(st + 3 * TILEB + sw, BlE + kb);
        }
        CP_COMMIT();
    };

    const uint32_t aRowB = (uint32_t)(warp_m * 32 + (lane & 15)) * 128 + ((lane >> 4) << 4);
    const uint32_t bRowB = (uint32_t)(warp_n * 32 + (lane & 7) + ((lane >> 4) << 3)) * 128
                         + (((lane >> 3) & 1) << 4);

    load_stage(0);
    load_stage(1);

    for (int i = 0; i < nIter; i++) {
        CP_WAIT1();                 // stage i complete (i+1 may be in flight)
        __syncthreads();            // all warps past compute(i-1): WAR-safe
        if (i + 2 < nIter) load_stage(i + 2);   // overlaps with compute(i)
        else CP_COMMIT();           // keep wait_group 1 exact

        const uint32_t st  = sbase + (uint32_t)(i % NSTAGE) * STAGEB;
        const uint32_t tAh = st, tAl = st + TILEB;
        const uint32_t tBh = st + 2 * TILEB, tBl = st + 3 * TILEB;

#pragma unroll
        for (int kc = 0; kc < 4; kc++) {
            const uint32_t kB = (uint32_t)kc * 32;
            uint32_t a[2][4], bh[4][2];
#pragma unroll
            for (int mi = 0; mi < 2; mi++)
                ldm_x4(a[mi], tAh + swz(aRowB + (uint32_t)(mi * 16) * 128 + kB));
#pragma unroll
            for (int np = 0; np < 2; np++) {
                uint32_t r[4];
                ldm_x4(r, tBh + swz(bRowB + (uint32_t)(np * 16) * 128 + kB));
                bh[2 * np][0] = r[0]; bh[2 * np][1] = r[1];
                bh[2 * np + 1][0] = r[2]; bh[2 * np + 1][1] = r[3];
            }
#pragma unroll
            for (int mi = 0; mi < 2; mi++)
#pragma unroll
                for (int ni = 0; ni < 4; ni++)
                    mma16816(acc[mi][ni], a[mi], bh[ni]);          // hi*hi
            {
                uint32_t bl[4][2];
#pragma unroll
                for (int np = 0; np < 2; np++) {
                    uint32_t r[4];
                    ldm_x4(r, tBl + swz(bRowB + (uint32_t)(np * 16) * 128 + kB));
                    bl[2 * np][0] = r[0]; bl[2 * np][1] = r[1];
                    bl[2 * np + 1][0] = r[2]; bl[2 * np + 1][1] = r[3];
                }
#pragma unroll
                for (int mi = 0; mi < 2; mi++)
#pragma unroll
                    for (int ni = 0; ni < 4; ni++)
                        mma16816(acc[mi][ni], a[mi], bl[ni]);      // hi*lo
            }
            if (NPROD == 3) {
                if (useLo) {
#pragma unroll
                    for (int mi = 0; mi < 2; mi++)
                        ldm_x4(a[mi], tAl + swz(aRowB + (uint32_t)(mi * 16) * 128 + kB));
#pragma unroll
                    for (int mi = 0; mi < 2; mi++)
#pragma unroll
                        for (int ni = 0; ni < 4; ni++)
                            mma16816(acc[mi][ni], a[mi], bh[ni]);  // lo*hi
                }
            }
        }
    }
    __syncthreads();   // all compute done before epilogue reuses smem

    // ---- epilogue: accum -> smem (fp32, stride 132) -> coalesced global ----
    float* sEpi = (float*)smem;                 // 128 x 132 floats
    {
        const int r0 = warp_m * 32 + (lane >> 2);
        const int c0 = warp_n * 32 + 2 * (lane & 3);
#pragma unroll
        for (int mi = 0; mi < 2; mi++)
#pragma unroll
            for (int ni = 0; ni < 4; ni++) {
                const int rr = r0 + mi * 16;
                const int cc = c0 + ni * 8;
                sEpi[rr * 132 + cc]           = acc[mi][ni][0];
                sEpi[rr * 132 + cc + 1]       = acc[mi][ni][1];
                sEpi[(rr + 8) * 132 + cc]     = acc[mi][ni][2];
                sEpi[(rr + 8) * 132 + cc + 1] = acc[mi][ni][3];
            }
    }
    __syncthreads();

    if (EPI == 2) {
        float* Co = (MODE == 2 && bz == 1) ? CfAlt : Cf;
#pragma unroll
        for (int j = 0; j < 8; j++) {
            const int idx = tid + j * NTHR;      // 0..4095 float4s
            const int row = idx >> 5, c4 = (idx & 31) << 2;
            float4 v = *reinterpret_cast<const float4*>(&sEpi[row * 132 + c4]);
            v.x *= alpha; v.y *= alpha; v.z *= alpha; v.w *= alpha;
            *reinterpret_cast<float4*>(Co + (size_t)(by * BM + row) * ldc + bx * BN + c4) = v;
        }
    } else {  // EPI == 3: QKV dispatch
        if (wsel < 2) {
            __half* Oh = wsel ? Kh : Qh;
            __half* Ol = wsel ? Kl : Ql;
#pragma unroll
            for (int j = 0; j < 16; j++) {
                const int idx = tid + j * NTHR;  // 0..8191 half2s
                const int row = idx >> 6, c2 = (idx & 63) << 1;
                const size_t o = (size_t)(by * BM + row) * SD + bCol0 + c2;
                split_store2(Oh, Ol, o, sEpi[row * 132 + c2], sEpi[row * 132 + c2 + 1]);
            }
        } else {  // V: transposed split store
#pragma unroll
            for (int j = 0; j < 16; j++) {
                const int idx = tid + j * NTHR;
                const int c = idx >> 6;              // feature in tile, 0..127
                const int r2 = (idx & 63) << 1;      // two consecutive tokens
                const size_t o = (size_t)(bCol0 + c) * SN + by * BM + r2;
                split_store2(Vth, Vtl, o, sEpi[r2 * 132 + c], sEpi[(r2 + 1) * 132 + c]);
            }
        }
    }
}

// ------------------------- split / transpose -------------------------------
__global__ void __launch_bounds__(256)
split_kernel(const float* __restrict__ in, __half* __restrict__ h,
             __half* __restrict__ l, int n)
{
    int i = blockIdx.x * 256 + threadIdx.x;
    if (i < n) {
        float v = in[i];
        __half hh = __float2half(v);
        h[i] = hh;
        l[i] = __float2half(v - __half2float(hh));
    }
}

// Fused transpose+split for all 3 weights (z = weight index).
__global__ void __launch_bounds__(512)
tsplit_kernel(const float* __restrict__ Wq, const float* __restrict__ Wk,
              const float* __restrict__ Wv,
              __half* __restrict__ Th, __half* __restrict__ Tl)
{
    __shared__ float t[32][33];
    const int bx = blockIdx.x, by = blockIdx.y, bz = blockIdx.z;
    const float* W = (bz == 0) ? Wq : (bz == 1) ? Wk : Wv;
    __half* ThW = Th + (size_t)bz * SD * SD;
    __half* TlW = Tl + (size_t)bz * SD * SD;

    const int txx = threadIdx.x;   // 0..15
    const int tyy = threadIdx.y;   // 0..31
    {
        const float2 v = *reinterpret_cast<const float2*>(
            W + (size_t)(by * 32 + tyy) * SD + bx * 32 + 2 * txx);
        t[tyy][2 * txx]     = v.x;
        t[tyy][2 * txx + 1] = v.y;
    }
    __syncthreads();
    const int o  = bx * 32 + tyy;
    const int i0 = by * 32 + 2 * txx;
    const float v0 = t[2 * txx][tyy];
    const float v1 = t[2 * txx + 1][tyy];
    const __half h0 = __float2half(v0), h1 = __float2half(v1);
    const __half l0 = __float2half(v0 - __half2float(h0));
    const __half l1 = __float2half(v1 - __half2float(h1));
    *reinterpret_cast<__half2*>(ThW + (size_t)o * SD + i0) = __halves2half2(h0, h1);
    *reinterpret_cast<__half2*>(TlW + (size_t)o * SD + i0) = __halves2half2(l0, l1);
}

// ------------------------- softmax (fp32 -> Ph only) -----------------------
#define SMT 512
__global__ void __launch_bounds__(SMT)
softmax_kernel(const float* __restrict__ S, __half* __restrict__ Ph,
               const int* __restrict__ maskedp)
{
    __shared__ float sh[SN];
    __shared__ float red[SMT];
    const int r = blockIdx.x;
    const int msk = *maskedp;
    const int lim = msk ? (r + 1) : SN;
    const int limw = msk ? ((lim + 127) & ~127) : SN;   // PV never reads past this
    const int tid = threadIdx.x;

    float m = -CUDART_INF_F;
    for (int j = tid; j < lim; j += SMT) {
        float v = S[(size_t)r * SN + j];
        sh[j] = v;
        m = fmaxf(m, v);
    }
    red[tid] = m; __syncthreads();
    for (int s = SMT / 2; s > 0; s >>= 1) {
        if (tid < s) red[tid] = fmaxf(red[tid], red[tid + s]);
        __syncthreads();
    }
    const float rowmax = red[0]; __syncthreads();

    float sum = 0.0f;
    for (int j = tid; j < lim; j += SMT) {
        float e = expf(sh[j] - rowmax);
        sh[j] = e;
        sum += e;
    }
    red[tid] = sum; __syncthreads();
    for (int s = SMT / 2; s > 0; s >>= 1) {
        if (tid < s) red[tid] += red[tid + s];
        __syncthreads();
    }
    const float inv = 1.0f / red[0]; __syncthreads();

    for (int j = tid; j < limw; j += SMT) {
        float p = (j < lim) ? sh[j] * inv : 0.0f;
        Ph[(size_t)r * SN + j] = __float2half(p);
    }
}

// ------------------------- PV split-K reduce -------------------------------
__global__ void __launch_bounds__(256)
add_kernel(float* __restrict__ out, const float* __restrict__ part,
           const int* __restrict__ maskedp)
{
    const int msk = *maskedp;
    const size_t i = ((size_t)blockIdx.x * 256 + threadIdx.x) * 4;
    const int row = (int)(i >> 10);             // /SD
    if (msk && row < 128) return;               // by=0's z=1 slice was empty
    float4 a = *reinterpret_cast<const float4*>(out + i);
    float4 b = *reinterpret_cast<const float4*>(part + i);
    a.x += b.x; a.y += b.y; a.z += b.z; a.w += b.w;
    *reinterpret_cast<float4*>(out + i) = a;
}

// ------------------------- host --------------------------------------------
extern "C" void kernel_launch(void* const* d_in, const int* in_sizes, int n_in,
                              void* d_out, int out_size)
{
    (void)in_sizes; (void)n_in; (void)out_size;
    const float* x      = (const float*)d_in[0];
    const float* Wq     = (const float*)d_in[1];
    const float* Wk     = (const float*)d_in[2];
    const float* Wv     = (const float*)d_in[3];
    const int*   masked = (const int*)d_in[4];
    float* out = (float*)d_out;

    float *S, *O2;
    __half *xh, *xl, *Wth, *Wtl, *Qh, *Ql, *Kh, *Kl, *Vth, *Vtl, *Ph;
    cudaGetSymbolAddress((void**)&S,   g_S);
    cudaGetSymbolAddress((void**)&O2,  g_O2);
    cudaGetSymbolAddress((void**)&xh,  g_xh);
    cudaGetSymbolAddress((void**)&xl,  g_xl);
    cudaGetSymbolAddress((void**)&Wth, g_Wth);
    cudaGetSymbolAddress((void**)&Wtl, g_Wtl);
    cudaGetSymbolAddress((void**)&Qh,  g_Qh);
    cudaGetSymbolAddress((void**)&Ql,  g_Ql);
    cudaGetSymbolAddress((void**)&Kh,  g_Kh);
    cudaGetSymbolAddress((void**)&Kl,  g_Kl);
    cudaGetSymbolAddress((void**)&Vth, g_Vth);
    cudaGetSymbolAddress((void**)&Vtl, g_Vtl);
    cudaGetSymbolAddress((void**)&Ph,  g_Ph);

    cudaFuncSetAttribute(mm_kernel<0,3,3>, cudaFuncAttributeMaxDynamicSharedMemorySize, SMEMB);
    cudaFuncSetAttribute(mm_kernel<1,2,3>, cudaFuncAttributeMaxDynamicSharedMemorySize, SMEMB);
    cudaFuncSetAttribute(mm_kernel<2,2,2>, cudaFuncAttributeMaxDynamicSharedMemorySize, SMEMB);

    // prep
    split_kernel<<<(SN * SD + 255) / 256, 256>>>(x, xh, xl, SN * SD);
    tsplit_kernel<<<dim3(32, 32, 3), dim3(16, 32)>>>(Wq, Wk, Wv, Wth, Wtl);

    const float scale = 1.0f / 32.0f;

    // fused QKV projections (24 = 3 weights x 8 col tiles; V CTAs 2-product)
    dim3 gqkv(24, SN / BM);
    mm_kernel<0,3,3><<<gqkv, NTHR, SMEMB>>>(xh, xl, SD, Wth, Wtl, SD, SD, 1.0f,
                                            nullptr, nullptr, Qh, Ql, Kh, Kl, Vth, Vtl,
                                            0, masked);
    // scores
    dim3 gs(SN / BN, SN / BM);
    mm_kernel<1,2,3><<<gs, NTHR, SMEMB>>>(Qh, Ql, SD, Kh, Kl, SD, SD, scale,
                                          S, nullptr, nullptr, nullptr, nullptr,
                                          nullptr, nullptr, nullptr, SN, masked);
    softmax_kernel<<<SN, SMT>>>(S, Ph, masked);
    // PV: balanced 2-way split-K (heavy rows first) into out / O2, then add
    dim3 gv(SD / BN, SN / BM, 2);
    mm_kernel<2,2,2><<<gv, NTHR, SMEMB>>>(Ph, Ph, SN, Vth, Vtl, SN, SN, 1.0f,
                                          out, O2, nullptr, nullptr, nullptr,
                                          nullptr, nullptr, nullptr, SD, masked);
    add_kernel<<<(SN * SD) / 1024, 256>>>(out, O2, masked);
}

// round 17
// speedup vs baseline: 1.0269x; 1.0269x over previous
#include <cuda_runtime.h>
#include <cuda_fp16.h>
#include <math_constants.h>
#include <cstdint>

// ---------------------------------------------------------------------------
// SelfAttention via split-fp16 mma.sync GEMMs (fp32-accurate; plain sm_103).
// a = a_hi + a_lo (fp16 each); GEMMs use 3 products (Ah@Bh + Ah@Bl + Al@Bh);
// PV uses 2 (Pl dropped); V projection uses 2 (x_lo dropped).
// Round 17: R12 tile (128x256, warp 64x32, NSTAGE=2 — best B/MAC) with a
// single-barrier depth-1-prefetch loop: wait0 -> sync -> load(i+1) ->
// compute(i). Halves barriers/iter and removes the end-of-iter load convoy.
// (R13's 128x128/3-stage regressed: worse smem bytes/MAC; crossbar co-limit.)
// ---------------------------------------------------------------------------

#define SN 4096
#define SD 1024
#define BM 128
#define BN 256
#define BKE 64                    // K elems (fp16) per stage = 128 bytes/row
#define NSTAGE 2
#define NTHR 512
#define ATILEB 16384              // 128 rows x 128 bytes
#define BTILEB 32768              // 256 rows x 128 bytes
#define STAGEB (2 * ATILEB + 2 * BTILEB)   // 98304
#define SMEMB (NSTAGE * STAGEB)   // 196608 bytes

// ------------------------- scratch ----------------------------------------
static __device__ float   g_S[(size_t)SN * SN];
static __device__ float   g_O2[(size_t)SN * SD];
static __device__ __half  g_xh[SN * SD],  g_xl[SN * SD];
static __device__ __half  g_Wth[3][SD * SD], g_Wtl[3][SD * SD];
static __device__ __half  g_Qh[SN * SD],  g_Ql[SN * SD];
static __device__ __half  g_Kh[SN * SD],  g_Kl[SN * SD];
static __device__ __half  g_Vth[(size_t)SD * SN], g_Vtl[(size_t)SD * SN];
static __device__ __half  g_Ph[(size_t)SN * SN];

// ------------------------- PTX helpers ------------------------------------
__device__ __forceinline__ uint32_t smem_u32(const void* p) {
    uint32_t a;
    asm("{ .reg .u64 t; cvta.to.shared.u64 t, %1; cvt.u32.u64 %0, t; }"
        : "=r"(a) : "l"(p));
    return a;
}
__device__ __forceinline__ uint32_t swz(uint32_t o) { return o ^ ((o >> 3) & 0x70); }

__device__ __forceinline__ void cp16(uint32_t dst, const void* src) {
    asm volatile("cp.async.cg.shared.global [%0], [%1], 16;\n" :: "r"(dst), "l"(src));
}
#define CP_COMMIT() asm volatile("cp.async.commit_group;\n" ::: "memory")
#define CP_WAIT0()  asm volatile("cp.async.wait_group 0;\n" ::: "memory")

__device__ __forceinline__ void ldm_x4(uint32_t* r, uint32_t addr) {
    asm volatile("ldmatrix.sync.aligned.m8n8.x4.shared.b16 {%0,%1,%2,%3}, [%4];"
        : "=r"(r[0]), "=r"(r[1]), "=r"(r[2]), "=r"(r[3]) : "r"(addr));
}
__device__ __forceinline__ void mma16816(float* c, const uint32_t* a, const uint32_t* b) {
    asm volatile("mma.sync.aligned.m16n8k16.row.col.f32.f16.f16.f32 "
        "{%0,%1,%2,%3}, {%4,%5,%6,%7}, {%8,%9}, {%0,%1,%2,%3};"
        : "+f"(c[0]), "+f"(c[1]), "+f"(c[2]), "+f"(c[3])
        : "r"(a[0]), "r"(a[1]), "r"(a[2]), "r"(a[3]), "r"(b[0]), "r"(b[1]));
}

__device__ __forceinline__ void split_store2(__half* Hh, __half* Hl, size_t o,
                                             float v0, float v1) {
    const __half h0 = __float2half(v0), h1 = __float2half(v1);
    const __half l0 = __float2half(v0 - __half2float(h0));
    const __half l1 = __float2half(v1 - __half2float(h1));
    *reinterpret_cast<__half2*>(Hh + o) = __halves2half2(h0, h1);
    *reinterpret_cast<__half2*>(Hl + o) = __halves2half2(l0, l1);
}

// ------------------------- GEMM kernel -------------------------------------
// 512 threads, 16 warps: warp grid 2(m) x 8(n), warp tile 64x32.
// MODE 0: plain. MODE 1: scores (skip tiles fully above diag when masked).
// MODE 2: PV (K truncated at diagonal; per-row balanced 2-way split-K over bz,
//         heavy row-blocks first; bz=1 -> CfAlt).
// EPI 2: fp32 store alpha*C. EPI 3: fused QKV dispatch (bx>>2 selects weight;
//        w<2 -> row-major split store (Q/K), w==2 -> transposed split (V^T),
//        V CTAs drop the x_lo product at runtime).
// NPROD: 3 = full split, 2 = skip A_lo (loads and MMAs).
template <int MODE, int EPI, int NPROD>
__global__ void __launch_bounds__(NTHR, 1)
mm_kernel(const __half* __restrict__ Ah, const __half* __restrict__ Al, int lda,
          const __half* __restrict__ Bh, const __half* __restrict__ Bl, int ldb,
          int Kdim, float alpha,
          float* __restrict__ Cf, float* __restrict__ CfAlt,
          __half* __restrict__ Qh, __half* __restrict__ Ql,
          __half* __restrict__ Kh, __half* __restrict__ Kl,
          __half* __restrict__ Vth, __half* __restrict__ Vtl,
          int ldc, const int* __restrict__ maskedp)
{
    const int bx = blockIdx.x, bz = blockIdx.z;
    // MODE 2: reverse row order so the longest-K CTAs start in wave 1.
    const int by = (MODE == 2) ? (gridDim.y - 1 - blockIdx.y) : blockIdx.y;
    const int msk = *maskedp;
    if (MODE == 1 && msk && 2 * bx > by) return;

    int kStart = 0, kEnd = Kdim;
    if (MODE == 2) {
        const int kFull = msk ? (by + 1) * BM : Kdim;
        const int h = ((kFull >> 1) + 127) & ~127;       // balanced, 128-aligned
        if (bz == 0) { kStart = 0; kEnd = h; }
        else         { kStart = h; kEnd = kFull; }
        if (kStart >= kEnd) return;                      // by=0, z=1
    }
    const int nIter = (kEnd - kStart) / BKE;    // >= 2 always

    // effective B pointer / column base (EPI3 packs 3 weights along bx)
    const __half* BhE = Bh;
    const __half* BlE = Bl;
    int bCol0 = bx * BN;
    int wsel = 0;
    if (EPI == 3) {
        wsel = bx >> 2;
        BhE = Bh + (size_t)wsel * SD * SD;
        BlE = Bl + (size_t)wsel * SD * SD;
        bCol0 = (bx & 3) * BN;
    }
    // V projection: drop x_lo product (uniform per-CTA branch)
    const bool useLo = (NPROD == 3) && !(EPI == 3 && wsel == 2);

    extern __shared__ char smem[];
    const uint32_t sbase = smem_u32(smem);
    const int tid  = threadIdx.x;
    const int wid  = tid >> 5;
    const int lane = tid & 31;
    const int warp_m = wid & 1;                 // 2 x 64 rows
    const int warp_n = wid >> 1;                // 8 x 32 cols

    float acc[4][4][4];
#pragma unroll
    for (int mi = 0; mi < 4; mi++)
#pragma unroll
        for (int ni = 0; ni < 4; ni++)
#pragma unroll
            for (int r = 0; r < 4; r++) acc[mi][ni][r] = 0.0f;

    const int aRow0 = by * BM;

    auto load_stage = [&](int s) {
        const uint32_t st = sbase + (uint32_t)(s % NSTAGE) * STAGEB;
        const int kk = kStart + s * BKE;
#pragma unroll
        for (int j = 0; j < 2; j++) {           // A: 128 rows (hi, +lo if useLo)
            const int idx = tid + j * NTHR;     // 0..1023
            const int r = idx >> 3;
            const int c = idx & 7;
            const uint32_t sw = swz((uint32_t)(r * 128 + c * 16));
            const size_t ka = (size_t)(aRow0 + r) * lda + kk + c * 8;
            cp16(st + sw, Ah + ka);
            if (NPROD == 3) { if (useLo) cp16(st + ATILEB + sw, Al + ka); }
        }
#pragma unroll
        for (int j = 0; j < 4; j++) {           // B: 256 rows hi+lo
            const int idx = tid + j * NTHR;     // 0..2047
            const int r = idx >> 3;
            const int c = idx & 7;
            const uint32_t sw = swz((uint32_t)(r * 128 + c * 16));
            const size_t kb = (size_t)(bCol0 + r) * ldb + kk + c * 8;
            cp16(st + 2 * ATILEB + sw, BhE + kb);
            cp16(st + 2 * ATILEB + BTILEB + sw, BlE + kb);
        }
        CP_COMMIT();
    };

    const uint32_t aRowB = (uint32_t)(warp_m * 64 + (lane & 15)) * 128 + ((lane >> 4) << 4);
    const uint32_t bRowB = (uint32_t)(warp_n * 32 + (lane & 7) + ((lane >> 4) << 3)) * 128
                         + (((lane >> 3) & 1) << 4);

    load_stage(0);

    for (int i = 0; i < nIter; i++) {
        CP_WAIT0();                 // load(i) complete (sole pending group)
        __syncthreads();            // compute(i-1) done in all warps: WAR-safe
        if (i + 1 < nIter) load_stage(i + 1);   // overlaps with compute(i)

        const uint32_t st  = sbase + (uint32_t)(i % NSTAGE) * STAGEB;
        const uint32_t tAh = st, tAl = st + ATILEB;
        const uint32_t tBh = st + 2 * ATILEB, tBl = tBh + BTILEB;

#pragma unroll
        for (int kc = 0; kc < 4; kc++) {
            const uint32_t kB = (uint32_t)kc * 32;
            uint32_t a[4][4], bh[4][2];
#pragma unroll
            for (int mi = 0; mi < 4; mi++)
                ldm_x4(a[mi], tAh + swz(aRowB + (uint32_t)(mi * 16) * 128 + kB));
#pragma unroll
            for (int np = 0; np < 2; np++) {
                uint32_t r[4];
                ldm_x4(r, tBh + swz(bRowB + (uint32_t)(np * 16) * 128 + kB));
                bh[2 * np][0] = r[0]; bh[2 * np][1] = r[1];
                bh[2 * np + 1][0] = r[2]; bh[2 * np + 1][1] = r[3];
            }
#pragma unroll
            for (int mi = 0; mi < 4; mi++)
#pragma unroll
                for (int ni = 0; ni < 4; ni++)
                    mma16816(acc[mi][ni], a[mi], bh[ni]);          // hi*hi
            {
                uint32_t bl[4][2];
#pragma unroll
                for (int np = 0; np < 2; np++) {
                    uint32_t r[4];
                    ldm_x4(r, tBl + swz(bRowB + (uint32_t)(np * 16) * 128 + kB));
                    bl[2 * np][0] = r[0]; bl[2 * np][1] = r[1];
                    bl[2 * np + 1][0] = r[2]; bl[2 * np + 1][1] = r[3];
                }
#pragma unroll
                for (int mi = 0; mi < 4; mi++)
#pragma unroll
                    for (int ni = 0; ni < 4; ni++)
                        mma16816(acc[mi][ni], a[mi], bl[ni]);      // hi*lo
            }
            if (NPROD == 3) {
                if (useLo) {
#pragma unroll
                    for (int mi = 0; mi < 4; mi++)
                        ldm_x4(a[mi], tAl + swz(aRowB + (uint32_t)(mi * 16) * 128 + kB));
#pragma unroll
                    for (int mi = 0; mi < 4; mi++)
#pragma unroll
                        for (int ni = 0; ni < 4; ni++)
                            mma16816(acc[mi][ni], a[mi], bh[ni]);  // lo*hi
                }
            }
        }
    }
    __syncthreads();   // all compute done before epilogue reuses smem

    // ---- epilogue: accum -> smem (fp32, stride 260) -> coalesced global ----
    float* sEpi = (float*)smem;                 // 128 x 260 floats
    {
        const int r0 = warp_m * 64 + (lane >> 2);
        const int c0 = warp_n * 32 + 2 * (lane & 3);
#pragma unroll
        for (int mi = 0; mi < 4; mi++)
#pragma unroll
            for (int ni = 0; ni < 4; ni++) {
                const int rr = r0 + mi * 16;
                const int cc = c0 + ni * 8;
                sEpi[rr * 260 + cc]           = acc[mi][ni][0];
                sEpi[rr * 260 + cc + 1]       = acc[mi][ni][1];
                sEpi[(rr + 8) * 260 + cc]     = acc[mi][ni][2];
                sEpi[(rr + 8) * 260 + cc + 1] = acc[mi][ni][3];
            }
    }
    __syncthreads();

    if (EPI == 2) {
        float* Co = (MODE == 2 && bz == 1) ? CfAlt : Cf;
#pragma unroll
        for (int j = 0; j < 16; j++) {
            const int idx = tid + j * NTHR;      // 0..8191 float4s
            const int row = idx >> 6, c4 = (idx & 63) << 2;
            float4 v = *reinterpret_cast<const float4*>(&sEpi[row * 260 + c4]);
            v.x *= alpha; v.y *= alpha; v.z *= alpha; v.w *= alpha;
            *reinterpret_cast<float4*>(Co + (size_t)(by * BM + row) * ldc + bx * BN + c4) = v;
        }
    } else {  // EPI == 3: QKV dispatch
        if (wsel < 2) {
            __half* Oh = wsel ? Kh : Qh;
            __half* Ol = wsel ? Kl : Ql;
#pragma unroll
            for (int j = 0; j < 32; j++) {
                const int idx = tid + j * NTHR;  // 0..16383 half2s
                const int row = idx >> 7, c2 = (idx & 127) << 1;
                const size_t o = (size_t)(by * BM + row) * SD + bCol0 + c2;
                split_store2(Oh, Ol, o, sEpi[row * 260 + c2], sEpi[row * 260 + c2 + 1]);
            }
        } else {  // V: transposed split store
#pragma unroll
            for (int j = 0; j < 32; j++) {
                const int idx = tid + j * NTHR;
                const int c = idx >> 6;              // feature in tile, 0..255
                const int r2 = (idx & 63) << 1;      // two consecutive tokens
                const size_t o = (size_t)(bCol0 + c) * SN + by * BM + r2;
                split_store2(Vth, Vtl, o, sEpi[r2 * 260 + c], sEpi[(r2 + 1) * 260 + c]);
            }
        }
    }
}

// ------------------------- split / transpose -------------------------------
__global__ void __launch_bounds__(256)
split_kernel(const float* __restrict__ in, __half* __restrict__ h,
             __half* __restrict__ l, int n)
{
    int i = blockIdx.x * 256 + threadIdx.x;
    if (i < n) {
        float v = in[i];
        __half hh = __float2half(v);
        h[i] = hh;
        l[i] = __float2half(v - __half2float(hh));
    }
}

// Fused transpose+split for all 3 weights (z = weight index).
__global__ void __launch_bounds__(512)
tsplit_kernel(const float* __restrict__ Wq, const float* __restrict__ Wk,
              const float* __restrict__ Wv,
              __half* __restrict__ Th, __half* __restrict__ Tl)
{
    __shared__ float t[32][33];
    const int bx = blockIdx.x, by = blockIdx.y, bz = blockIdx.z;
    const float* W = (bz == 0) ? Wq : (bz == 1) ? Wk : Wv;
    __half* ThW = Th + (size_t)bz * SD * SD;
    __half* TlW = Tl + (size_t)bz * SD * SD;

    const int txx = threadIdx.x;   // 0..15
    const int tyy = threadIdx.y;   // 0..31
    {
        const float2 v = *reinterpret_cast<const float2*>(
            W + (size_t)(by * 32 + tyy) * SD + bx * 32 + 2 * txx);
        t[tyy][2 * txx]     = v.x;
        t[tyy][2 * txx + 1] = v.y;
    }
    __syncthreads();
    const int o  = bx * 32 + tyy;
    const int i0 = by * 32 + 2 * txx;
    const float v0 = t[2 * txx][tyy];
    const float v1 = t[2 * txx + 1][tyy];
    const __half h0 = __float2half(v0), h1 = __float2half(v1);
    const __half l0 = __float2half(v0 - __half2float(h0));
    const __half l1 = __float2half(v1 - __half2float(h1));
    *reinterpret_cast<__half2*>(ThW + (size_t)o * SD + i0) = __halves2half2(h0, h1);
    *reinterpret_cast<__half2*>(TlW + (size_t)o * SD + i0) = __halves2half2(l0, l1);
}

// ------------------------- softmax (fp32 -> Ph only) -----------------------
#define SMT 512
__global__ void __launch_bounds__(SMT)
softmax_kernel(const float* __restrict__ S, __half* __restrict__ Ph,
               const int* __restrict__ maskedp)
{
    __shared__ float sh[SN];
    __shared__ float red[SMT];
    const int r = blockIdx.x;
    const int msk = *maskedp;
    const int lim = msk ? (r + 1) : SN;
    const int limw = msk ? ((lim + 127) & ~127) : SN;   // PV never reads past this
    const int tid = threadIdx.x;

    float m = -CUDART_INF_F;
    for (int j = tid; j < lim; j += SMT) {
        float v = S[(size_t)r * SN + j];
        sh[j] = v;
        m = fmaxf(m, v);
    }
    red[tid] = m; __syncthreads();
    for (int s = SMT / 2; s > 0; s >>= 1) {
        if (tid < s) red[tid] = fmaxf(red[tid], red[tid + s]);
        __syncthreads();
    }
    const float rowmax = red[0]; __syncthreads();

    float sum = 0.0f;
    for (int j = tid; j < lim; j += SMT) {
        float e = expf(sh[j] - rowmax);
        sh[j] = e;
        sum += e;
    }
    red[tid] = sum; __syncthreads();
    for (int s = SMT / 2; s > 0; s >>= 1) {
        if (tid < s) red[tid] += red[tid + s];
        __syncthreads();
    }
    const float inv = 1.0f / red[0]; __syncthreads();

    for (int j = tid; j < limw; j += SMT) {
        float p = (j < lim) ? sh[j] * inv : 0.0f;
        Ph[(size_t)r * SN + j] = __float2half(p);
    }
}

// ------------------------- PV split-K reduce -------------------------------
__global__ void __launch_bounds__(256)
add_kernel(float* __restrict__ out, const float* __restrict__ part,
           const int* __restrict__ maskedp)
{
    const int msk = *maskedp;
    const size_t i = ((size_t)blockIdx.x * 256 + threadIdx.x) * 4;
    const int row = (int)(i >> 10);             // /SD
    if (msk && row < 128) return;               // by=0's z=1 slice was empty
    float4 a = *reinterpret_cast<const float4*>(out + i);
    float4 b = *reinterpret_cast<const float4*>(part + i);
    a.x += b.x; a.y += b.y; a.z += b.z; a.w += b.w;
    *reinterpret_cast<float4*>(out + i) = a;
}

// ------------------------- host --------------------------------------------
extern "C" void kernel_launch(void* const* d_in, const int* in_sizes, int n_in,
                              void* d_out, int out_size)
{
    (void)in_sizes; (void)n_in; (void)out_size;
    const float* x      = (const float*)d_in[0];
    const float* Wq     = (const float*)d_in[1];
    const float* Wk     = (const float*)d_in[2];
    const float* Wv     = (const float*)d_in[3];
    const int*   masked = (const int*)d_in[4];
    float* out = (float*)d_out;

    float *S, *O2;
    __half *xh, *xl, *Wth, *Wtl, *Qh, *Ql, *Kh, *Kl, *Vth, *Vtl, *Ph;
    cudaGetSymbolAddress((void**)&S,   g_S);
    cudaGetSymbolAddress((void**)&O2,  g_O2);
    cudaGetSymbolAddress((void**)&xh,  g_xh);
    cudaGetSymbolAddress((void**)&xl,  g_xl);
    cudaGetSymbolAddress((void**)&Wth, g_Wth);
    cudaGetSymbolAddress((void**)&Wtl, g_Wtl);
    cudaGetSymbolAddress((void**)&Qh,  g_Qh);
    cudaGetSymbolAddress((void**)&Ql,  g_Ql);
    cudaGetSymbolAddress((void**)&Kh,  g_Kh);
    cudaGetSymbolAddress((void**)&Kl,  g_Kl);
    cudaGetSymbolAddress((void**)&Vth, g_Vth);
    cudaGetSymbolAddress((void**)&Vtl, g_Vtl);
    cudaGetSymbolAddress((void**)&Ph,  g_Ph);

    cudaFuncSetAttribute(mm_kernel<0,3,3>, cudaFuncAttributeMaxDynamicSharedMemorySize, SMEMB);
    cudaFuncSetAttribute(mm_kernel<1,2,3>, cudaFuncAttributeMaxDynamicSharedMemorySize, SMEMB);
    cudaFuncSetAttribute(mm_kernel<2,2,2>, cudaFuncAttributeMaxDynamicSharedMemorySize, SMEMB);

    // prep
    split_kernel<<<(SN * SD + 255) / 256, 256>>>(x, xh, xl, SN * SD);
    tsplit_kernel<<<dim3(32, 32, 3), dim3(16, 32)>>>(Wq, Wk, Wv, Wth, Wtl);

    const float scale = 1.0f / 32.0f;

    // fused QKV projections (12 = 3 weights x 4 col tiles; V CTAs 2-product)
    dim3 gqkv(12, SN / BM);
    mm_kernel<0,3,3><<<gqkv, NTHR, SMEMB>>>(xh, xl, SD, Wth, Wtl, SD, SD, 1.0f,
                                            nullptr, nullptr, Qh, Ql, Kh, Kl, Vth, Vtl,
                                            0, masked);
    // scores
    dim3 gs(SN / BN, SN / BM);
    mm_kernel<1,2,3><<<gs, NTHR, SMEMB>>>(Qh, Ql, SD, Kh, Kl, SD, SD, scale,
                                          S, nullptr, nullptr, nullptr, nullptr,
                                          nullptr, nullptr, nullptr, SN, masked);
    softmax_kernel<<<SN, SMT>>>(S, Ph, masked);
    // PV: balanced 2-way split-K (heavy rows first) into out / O2, then add
    dim3 gv(SD / BN, SN / BM, 2);
    mm_kernel<2,2,2><<<gv, NTHR, SMEMB>>>(Ph, Ph, SN, Vth, Vtl, SN, SN, 1.0f,
                                          out, O2, nullptr, nullptr, nullptr,
                                          nullptr, nullptr, nullptr, SD, masked);
    add_kernel<<<(SN * SD) / 1024, 256>>>(out, O2, masked);
}